// round 13
// baseline (speedup 1.0000x reference)
#include <cuda_runtime.h>
#include <cuda_bf16.h>
#include <math.h>
#include <stdint.h>

#define BB     4
#define SS     2048
#define DM     768
#define NH     12
#define DKH    64
#define M_TOT  (BB*SS)   // 8192

// -------- scratch (static device arrays; no runtime allocation) --------
__device__ __nv_bfloat16 g_qkvb[3*M_TOT*DM];   // Q,K,V projections (bf16)
__device__ __nv_bfloat16 g_ab[3*M_TOT*DM];     // cast inputs / ctx (slice 0)
__device__ __nv_bfloat16 g_wb[4*DM*DM];        // cast weights x4
__device__ float    g_tmp[M_TOT*DM];
__device__ uint32_t g_mbits[BB*SS*(SS/32)];    // packed mask bits

// ============================================================================
// helpers
// ============================================================================
__device__ __forceinline__ uint32_t smem_u32(const void* p) {
    return (uint32_t)__cvta_generic_to_shared(p);
}
__device__ __forceinline__ void ldsm4(uint32_t& r0, uint32_t& r1, uint32_t& r2, uint32_t& r3, uint32_t addr) {
    asm volatile("ldmatrix.sync.aligned.m8n8.x4.shared.b16 {%0,%1,%2,%3}, [%4];"
                 : "=r"(r0), "=r"(r1), "=r"(r2), "=r"(r3) : "r"(addr));
}
__device__ __forceinline__ void ldsm4t(uint32_t& r0, uint32_t& r1, uint32_t& r2, uint32_t& r3, uint32_t addr) {
    asm volatile("ldmatrix.sync.aligned.m8n8.x4.trans.shared.b16 {%0,%1,%2,%3}, [%4];"
                 : "=r"(r0), "=r"(r1), "=r"(r2), "=r"(r3) : "r"(addr));
}
__device__ __forceinline__ void mma_bf16(float* c, uint32_t a0, uint32_t a1, uint32_t a2, uint32_t a3,
                                         uint32_t b0, uint32_t b1) {
    asm volatile("mma.sync.aligned.m16n8k16.row.col.f32.bf16.bf16.f32 "
                 "{%0,%1,%2,%3},{%4,%5,%6,%7},{%8,%9},{%0,%1,%2,%3};"
                 : "+f"(c[0]), "+f"(c[1]), "+f"(c[2]), "+f"(c[3])
                 : "r"(a0), "r"(a1), "r"(a2), "r"(a3), "r"(b0), "r"(b1));
}
__device__ __forceinline__ uint32_t pack_bf16(float x, float y) {
    __nv_bfloat162 p;
    p.x = __float2bfloat16(x);
    p.y = __float2bfloat16(y);
    return *(uint32_t*)&p;
}
__device__ __forceinline__ void cpasync16(uint32_t dst, const void* src) {
    asm volatile("cp.async.cg.shared.global [%0], [%1], 16;" :: "r"(dst), "l"(src));
}
__device__ __forceinline__ void cp_commit() { asm volatile("cp.async.commit_group;"); }
template<int N> __device__ __forceinline__ void cp_wait() {
    asm volatile("cp.async.wait_group %0;" :: "n"(N));
}

// ============================================================================
// Fused prep kernel: role by blockIdx.x range.
//  [0, 4096)            : mask pack (int32 -> bits)
//  [4096, 4096+2304)    : weight cast (4 x 576 blocks)
//  [6400, 6400+18432)   : input cast (3 x 6144 blocks)
// ============================================================================
#define NB_MASK 4096
#define NB_WCST 2304   // 4 * 576
#define NB_ICST 18432  // 3 * 6144
#define NB_PREP (NB_MASK + NB_WCST + NB_ICST)

__global__ __launch_bounds__(256) void prep_kernel(
    const int* __restrict__ mask, uint32_t* __restrict__ bits,
    const float* __restrict__ w0, const float* __restrict__ w1,
    const float* __restrict__ w2, const float* __restrict__ w3,
    __nv_bfloat16* __restrict__ wdst,
    const float* __restrict__ x0, const float* __restrict__ x1,
    const float* __restrict__ x2, __nv_bfloat16* __restrict__ xdst)
{
    const int bid = blockIdx.x;
    const int tid = threadIdx.x;

    if (bid < NB_MASK) {
        // mask pack: each warp packs 16 words (16*32 ints)
        const int warp = (bid * 256 + tid) >> 5;
        const int lane = tid & 31;
        const size_t base = (size_t)warp * 16 * 32;
        #pragma unroll
        for (int i = 0; i < 16; i++) {
            int v = mask[base + i * 32 + lane];
            unsigned bal = __ballot_sync(0xffffffffu, v != 0);
            if (lane == 0) bits[warp * 16 + i] = bal;
        }
    } else if (bid < NB_MASK + NB_WCST) {
        const int idx = bid - NB_MASK;
        const int z   = idx / 576;
        const int blk = idx % 576;
        const float* x = (z == 0) ? w0 : (z == 1) ? w1 : (z == 2) ? w2 : w3;
        const size_t i = ((size_t)blk * 256 + tid) * 4;
        float4 v = *(const float4*)(x + i);
        __nv_bfloat16 h[4];
        h[0] = __float2bfloat16(v.x);
        h[1] = __float2bfloat16(v.y);
        h[2] = __float2bfloat16(v.z);
        h[3] = __float2bfloat16(v.w);
        *(uint2*)(wdst + (size_t)z * DM * DM + i) = *(uint2*)h;
    } else {
        const int idx = bid - NB_MASK - NB_WCST;
        const int z   = idx / 6144;
        const int blk = idx % 6144;
        const float* x = (z == 0) ? x0 : (z == 1) ? x1 : x2;
        const size_t i = ((size_t)blk * 256 + tid) * 4;
        float4 v = *(const float4*)(x + i);
        __nv_bfloat16 h[4];
        h[0] = __float2bfloat16(v.x);
        h[1] = __float2bfloat16(v.y);
        h[2] = __float2bfloat16(v.z);
        h[3] = __float2bfloat16(v.w);
        *(uint2*)(xdst + (size_t)z * M_TOT * DM + i) = *(uint2*)h;
    }
}

// ============================================================================
// bf16 tensor-core GEMM, 4-stage cp.async ring, ONE barrier per k-step,
// all ldsm batched before the MMA burst.
// 128x128 tile, BK=32, 8 warps (2m x 4n), warp tile 64x32.
// ============================================================================
#define AST 40    // A smem row stride (bf16): 80B -> ldsm conflict-free
#define BST 136   // B smem row stride (bf16): 272B -> ldsm.trans conflict-free
#define BK  32
#define NKT 24    // 768/32
#define GSTAGES 4
#define A_STAGE_BYTES (128*AST*2)   // 10240
#define B_STAGE_BYTES (BK*BST*2)    // 8704
#define GEMM_SMEM (GSTAGES*(A_STAGE_BYTES+B_STAGE_BYTES))   // 75776

template<bool MULTI, bool RESID, bool OUTBF16>
__global__ __launch_bounds__(256, 2) void gemm_tc_kernel(
    const __nv_bfloat16* __restrict__ Ag, const __nv_bfloat16* __restrict__ Wg,
    const float* __restrict__ b0, const float* __restrict__ b1,
    const float* __restrict__ b2,
    const float* __restrict__ resid, void* __restrict__ Cout)
{
    extern __shared__ __nv_bfloat16 smg[];
    const uint32_t as0 = smem_u32(smg);
    const uint32_t bs0 = as0 + GSTAGES * A_STAGE_BYTES;

    const int z = MULTI ? blockIdx.z : 0;
    const float* bias = MULTI ? ((z == 0) ? b0 : (z == 1) ? b1 : b2) : b0;
    const size_t a_base = (size_t)z * M_TOT * DM;
    const size_t w_base = (size_t)z * DM * DM;

    const int tid  = threadIdx.x;
    const int wid  = tid >> 5;
    const int lane = tid & 31;
    const int m0   = blockIdx.y * 128;
    const int n0   = blockIdx.x * 128;
    const int warp_m = (wid & 1) * 64;
    const int warp_n = (wid >> 1) * 32;

    const int sar = tid >> 1;            // A row 0..127
    const int sac = (tid & 1) * 16;      // A col 0 or 16
    const int sbr = tid >> 3;            // B k row 0..31
    const int sbc = (tid & 7) * 16;      // B n col

    const uint32_t a_off = (uint32_t)(sar * AST + sac) * 2;
    const uint32_t b_off = (uint32_t)(sbr * BST + sbc) * 2;

    const __nv_bfloat16* a_src = Ag + a_base + (size_t)(m0 + sar) * DM + sac;
    const __nv_bfloat16* b_src = Wg + w_base + (size_t)sbr * DM + n0 + sbc;

    const int lrow = lane & 7;
    const int lsel = lane >> 3;
    const int arow_f = lrow + ((lsel & 1) ? 8 : 0);
    const int akb    = (lsel & 2) ? 16 : 0;
    const int bkr    = lrow + ((lsel & 1) ? 8 : 0);
    const int bn_sub = (lsel & 2) ? 8 : 0;

    float acc[4][4][4] = {};

    auto fill = [&](int kt) {
        const int s = kt % GSTAGES;
        const uint32_t sa = as0 + (uint32_t)(s * A_STAGE_BYTES);
        const uint32_t sb = bs0 + (uint32_t)(s * B_STAGE_BYTES);
        const int k0 = kt * BK;
        cpasync16(sa + a_off,      a_src + k0);
        cpasync16(sa + a_off + 16, a_src + k0 + 8);
        cpasync16(sb + b_off,      b_src + (size_t)k0 * DM);
        cpasync16(sb + b_off + 16, b_src + (size_t)k0 * DM + 8);
        cp_commit();
    };

    fill(0);
    fill(1);
    fill(2);

    for (int kt = 0; kt < NKT; kt++) {
        if (kt == NKT - 1) cp_wait<0>(); else cp_wait<GSTAGES - 2>();
        __syncthreads();
        if (kt + GSTAGES - 1 < NKT) fill(kt + GSTAGES - 1);

        const int s = kt % GSTAGES;
        const uint32_t as_s = as0 + (uint32_t)(s * A_STAGE_BYTES);
        const uint32_t bs_s = bs0 + (uint32_t)(s * B_STAGE_BYTES);

        #pragma unroll
        for (int kk = 0; kk < 2; kk++) {
            // batch ALL loads for this kk before any mma
            uint32_t af[4][4];
            #pragma unroll
            for (int t = 0; t < 4; t++)
                ldsm4(af[t][0], af[t][1], af[t][2], af[t][3],
                      as_s + (uint32_t)((warp_m + t*16 + arow_f) * AST * 2 + kk*32 + akb));
            uint32_t bu0[4], bu1[4];
            ldsm4t(bu0[0], bu0[1], bu0[2], bu0[3],
                   bs_s + (uint32_t)((kk*16 + bkr) * BST * 2 + (warp_n + bn_sub) * 2));
            ldsm4t(bu1[0], bu1[1], bu1[2], bu1[3],
                   bs_s + (uint32_t)((kk*16 + bkr) * BST * 2 + (warp_n + 16 + bn_sub) * 2));
            #pragma unroll
            for (int t = 0; t < 4; t++) {
                mma_bf16(acc[t][0], af[t][0], af[t][1], af[t][2], af[t][3], bu0[0], bu0[1]);
                mma_bf16(acc[t][1], af[t][0], af[t][1], af[t][2], af[t][3], bu0[2], bu0[3]);
                mma_bf16(acc[t][2], af[t][0], af[t][1], af[t][2], af[t][3], bu1[0], bu1[1]);
                mma_bf16(acc[t][3], af[t][0], af[t][1], af[t][2], af[t][3], bu1[2], bu1[3]);
            }
        }
    }

    // epilogue
    const int g  = lane >> 2;
    const int t4 = lane & 3;
    #pragma unroll
    for (int t = 0; t < 4; t++) {
        #pragma unroll
        for (int n = 0; n < 4; n++) {
            int row0 = m0 + warp_m + t*16 + g;
            int row1 = row0 + 8;
            int col  = n0 + warp_n + n*8 + t4*2;
            float2 bi = *(const float2*)(bias + col);
            float2 o0, o1;
            o0.x = acc[t][n][0] + bi.x;  o0.y = acc[t][n][1] + bi.y;
            o1.x = acc[t][n][2] + bi.x;  o1.y = acc[t][n][3] + bi.y;
            if (RESID) {
                float2 r0 = *(const float2*)(resid + (size_t)row0 * DM + col);
                float2 r1 = *(const float2*)(resid + (size_t)row1 * DM + col);
                o0.x += r0.x; o0.y += r0.y;
                o1.x += r1.x; o1.y += r1.y;
            }
            if (OUTBF16) {
                __nv_bfloat16* C = (__nv_bfloat16*)Cout + (size_t)z * M_TOT * DM;
                *(uint32_t*)(C + (size_t)row0 * DM + col) = pack_bf16(o0.x, o0.y);
                *(uint32_t*)(C + (size_t)row1 * DM + col) = pack_bf16(o1.x, o1.y);
            } else {
                float* C = (float*)Cout;
                *(float2*)(C + (size_t)row0 * DM + col) = o0;
                *(float2*)(C + (size_t)row1 * DM + col) = o1;
            }
        }
    }
}

// ============================================================================
// Tensor-core flash attention, 3-stage cp.async ring, ONE barrier per tile.
// CTA: 128 q rows x one (b,h). 8 warps x 16 q rows. 64-key tiles.
// (unchanged from R11)
// ============================================================================
#define KST 72
#define ATT_STAGE_BYTES (2 * 64 * KST * 2)   // 18432
#define ASTAGES 3
#define ATT_SMEM (ASTAGES * ATT_STAGE_BYTES) // 55296
#define NTILES (SS/64)

__global__ __launch_bounds__(256, 2) void attn_tc_kernel(const uint32_t* __restrict__ mbits)
{
    extern __shared__ __nv_bfloat16 sma[];

    const int tid  = threadIdx.x;
    const int wid  = tid >> 5;
    const int lane = tid & 31;
    const int b    = blockIdx.z;
    const int h    = blockIdx.y;
    const int q0   = blockIdx.x * 128;
    const int g    = lane >> 2;
    const int t4   = lane & 3;

    const __nv_bfloat16* qg = g_qkvb + 0 * (size_t)M_TOT * DM;
    const __nv_bfloat16* kg = g_qkvb + 1 * (size_t)M_TOT * DM + (size_t)(b * SS) * DM + h * DKH;
    const __nv_bfloat16* vg = g_qkvb + 2 * (size_t)M_TOT * DM + (size_t)(b * SS) * DM + h * DKH;

    {
        const int r  = tid >> 1;
        const int hh = (tid & 1) * 32;
        const uint4* src = (const uint4*)(qg + (size_t)(b * SS + q0 + r) * DM + h * DKH + hh);
        uint4* dst = (uint4*)(sma + r * KST + hh);
        dst[0] = src[0]; dst[1] = src[1]; dst[2] = src[2]; dst[3] = src[3];
    }
    __syncthreads();

    uint32_t qa[4][4];
    {
        const uint32_t base = smem_u32(sma);
        const int row  = wid * 16 + (lane & 15);
        const int colh = (lane >> 4) * 8;
        #pragma unroll
        for (int j = 0; j < 4; j++)
            ldsm4(qa[j][0], qa[j][1], qa[j][2], qa[j][3],
                  base + (uint32_t)((row * KST + j * 16 + colh) * 2));
    }
    __syncthreads();

    float o[8][4] = {};
    float ls0 = 0.f, ls1 = 0.f;

    const uint32_t* mrow0 = mbits + ((size_t)(b * SS + q0 + wid * 16 + g)) * (SS/32);
    const uint32_t* mrow1 = mrow0 + 8 * (SS/32);

    const uint32_t sb = smem_u32(sma);

    const int krow = (lane & 7) + ((lane >> 4) ? 8 : 0);
    const int kcol = ((lane >> 3) & 1) * 8;
    const int vrow = (lane & 7) + (((lane >> 3) & 1) ? 8 : 0);
    const int vcol = (lane >> 4) * 8;
    const uint32_t k_lane_off = (uint32_t)((krow * KST + kcol) * 2);
    const uint32_t v_lane_off = (uint32_t)((vrow * KST + vcol) * 2) + (uint32_t)(64*KST*2);

    const int c0   = tid * 2;
    const int srow = c0 >> 3;
    const int scol = (c0 & 7) * 8;
    const uint32_t st_off = (uint32_t)((srow * KST + scol) * 2);

    auto fill = [&](int kt) {
        const uint32_t base = sb + (uint32_t)((kt % ASTAGES) * ATT_STAGE_BYTES);
        const __nv_bfloat16* kp = kg + (size_t)(kt * 64 + srow) * DM + scol;
        const __nv_bfloat16* vp = vg + (size_t)(kt * 64 + srow) * DM + scol;
        cpasync16(base + st_off, kp);
        cpasync16(base + st_off + 16, kp + 8);
        cpasync16(base + (uint32_t)(64*KST*2) + st_off, vp);
        cpasync16(base + (uint32_t)(64*KST*2) + st_off + 16, vp + 8);
        cp_commit();
    };

    fill(0);
    fill(1);

    for (int kt = 0; kt < NTILES; kt++) {
        if (kt == NTILES - 1) cp_wait<0>(); else cp_wait<ASTAGES - 2>();
        __syncthreads();
        if (kt + ASTAGES - 1 < NTILES) fill(kt + ASTAGES - 1);

        const uint32_t stage = sb + (uint32_t)((kt % ASTAGES) * ATT_STAGE_BYTES);
        const uint32_t kaddr0 = stage + k_lane_off;
        const uint32_t vaddr0 = stage + v_lane_off;

        float c[8][4] = {};
        #pragma unroll
        for (int np = 0; np < 4; np++) {
            #pragma unroll
            for (int j = 0; j < 4; j++) {
                uint32_t r0, r1, r2, r3;
                ldsm4(r0, r1, r2, r3, kaddr0 + (uint32_t)((np*16*KST + j*16) * 2));
                mma_bf16(c[2*np],   qa[j][0], qa[j][1], qa[j][2], qa[j][3], r0, r1);
                mma_bf16(c[2*np+1], qa[j][0], qa[j][1], qa[j][2], qa[j][3], r2, r3);
            }
        }

        const int k0 = kt * 64;
        const int kw = k0 >> 5;
        const uint32_t m0a = mrow0[kw], m0b = mrow0[kw+1];
        const uint32_t m1a = mrow1[kw], m1b = mrow1[kw+1];
        const float SC = 0.125f * 1.44269504088896340736f;
        #pragma unroll
        for (int nt = 0; nt < 8; nt++) {
            const int colb = nt * 8 + 2 * t4;
            const uint32_t w0 = (colb & 32) ? m0b : m0a;
            const uint32_t w1 = (colb & 32) ? m1b : m1a;
            const int bit = colb & 31;
            float p0 = ((w0 >> bit)     & 1u) ? 0.f : exp2f(c[nt][0] * SC);
            float p1 = ((w0 >> (bit+1)) & 1u) ? 0.f : exp2f(c[nt][1] * SC);
            float p2 = ((w1 >> bit)     & 1u) ? 0.f : exp2f(c[nt][2] * SC);
            float p3 = ((w1 >> (bit+1)) & 1u) ? 0.f : exp2f(c[nt][3] * SC);
            ls0 += p0 + p1;
            ls1 += p2 + p3;
            c[nt][0] = p0; c[nt][1] = p1; c[nt][2] = p2; c[nt][3] = p3;
        }

        uint32_t pa[4][4];
        #pragma unroll
        for (int j = 0; j < 4; j++) {
            pa[j][0] = pack_bf16(c[2*j][0],   c[2*j][1]);
            pa[j][1] = pack_bf16(c[2*j][2],   c[2*j][3]);
            pa[j][2] = pack_bf16(c[2*j+1][0], c[2*j+1][1]);
            pa[j][3] = pack_bf16(c[2*j+1][2], c[2*j+1][3]);
        }

        #pragma unroll
        for (int np = 0; np < 4; np++) {
            #pragma unroll
            for (int j = 0; j < 4; j++) {
                uint32_t r0, r1, r2, r3;
                ldsm4t(r0, r1, r2, r3, vaddr0 + (uint32_t)((j*16*KST + np*16) * 2));
                mma_bf16(o[2*np],   pa[j][0], pa[j][1], pa[j][2], pa[j][3], r0, r1);
                mma_bf16(o[2*np+1], pa[j][0], pa[j][1], pa[j][2], pa[j][3], r2, r3);
            }
        }
    }

    ls0 += __shfl_xor_sync(0xffffffffu, ls0, 1);
    ls0 += __shfl_xor_sync(0xffffffffu, ls0, 2);
    ls1 += __shfl_xor_sync(0xffffffffu, ls1, 1);
    ls1 += __shfl_xor_sync(0xffffffffu, ls1, 2);
    const float inv0 = 1.f / ls0;
    const float inv1 = 1.f / ls1;

    const size_t r0off = (size_t)(b * SS + q0 + wid * 16 + g) * DM + h * DKH;
    const size_t r1off = r0off + 8 * DM;
    #pragma unroll
    for (int nt = 0; nt < 8; nt++) {
        const int col = nt * 8 + 2 * t4;
        *(uint32_t*)(g_ab + r0off + col) = pack_bf16(o[nt][0] * inv0, o[nt][1] * inv0);
        *(uint32_t*)(g_ab + r1off + col) = pack_bf16(o[nt][2] * inv1, o[nt][3] * inv1);
    }
}

// ============================================================================
// LayerNorm: 1 block per row, 256 threads, 3 elements each
// ============================================================================
__global__ __launch_bounds__(256) void ln_kernel(
    const float* __restrict__ x,
    const float* __restrict__ gamma, const float* __restrict__ beta,
    float* __restrict__ out)
{
    const int row = blockIdx.x;
    const int tid = threadIdx.x;
    const float* xr = x + (size_t)row * DM;

    float v0 = xr[tid];
    float v1 = xr[tid + 256];
    float v2 = xr[tid + 512];
    float s  = v0 + v1 + v2;
    float sq = v0 * v0 + v1 * v1 + v2 * v2;

    #pragma unroll
    for (int o = 16; o > 0; o >>= 1) {
        s  += __shfl_xor_sync(0xffffffffu, s,  o);
        sq += __shfl_xor_sync(0xffffffffu, sq, o);
    }
    __shared__ float reds[8], redq[8];
    const int wid = tid >> 5, lid = tid & 31;
    if (lid == 0) { reds[wid] = s; redq[wid] = sq; }
    __syncthreads();
    float ts = 0.f, tq = 0.f;
    #pragma unroll
    for (int i = 0; i < 8; i++) { ts += reds[i]; tq += redq[i]; }

    const float mu  = ts * (1.f / DM);
    const float var = tq * (1.f / DM) - mu * mu;
    const float rs  = rsqrtf(var + 1e-5f);

    float* orow = out + (size_t)row * DM;
    orow[tid]       = (v0 - mu) * rs * gamma[tid]       + beta[tid];
    orow[tid + 256] = (v1 - mu) * rs * gamma[tid + 256] + beta[tid + 256];
    orow[tid + 512] = (v2 - mu) * rs * gamma[tid + 512] + beta[tid + 512];
}

// ============================================================================
// Launch
// ============================================================================
extern "C" void kernel_launch(void* const* d_in, const int* in_sizes, int n_in,
                              void* d_out, int out_size)
{
    const float* Qin  = (const float*)d_in[0];
    const float* Kin  = (const float*)d_in[1];
    const float* Vin  = (const float*)d_in[2];
    const int*   mask = (const int*)d_in[3];
    const float* Wq = (const float*)d_in[4];
    const float* bq = (const float*)d_in[5];
    const float* Wk = (const float*)d_in[6];
    const float* bk = (const float*)d_in[7];
    const float* Wv = (const float*)d_in[8];
    const float* bv = (const float*)d_in[9];
    const float* Wo = (const float*)d_in[10];
    const float* bo = (const float*)d_in[11];
    const float* gamma = (const float*)d_in[12];
    const float* beta  = (const float*)d_in[13];
    float* out = (float*)d_out;

    __nv_bfloat16 *gqkv, *gab, *gwb;
    float* gtmp;
    uint32_t* gmb;
    cudaGetSymbolAddress((void**)&gqkv, g_qkvb);
    cudaGetSymbolAddress((void**)&gab,  g_ab);
    cudaGetSymbolAddress((void**)&gwb,  g_wb);
    cudaGetSymbolAddress((void**)&gtmp, g_tmp);
    cudaGetSymbolAddress((void**)&gmb,  g_mbits);

    cudaFuncSetAttribute(gemm_tc_kernel<true, false, true>,
                         cudaFuncAttributeMaxDynamicSharedMemorySize, GEMM_SMEM);
    cudaFuncSetAttribute(gemm_tc_kernel<false, true, false>,
                         cudaFuncAttributeMaxDynamicSharedMemorySize, GEMM_SMEM);
    cudaFuncSetAttribute(attn_tc_kernel,
                         cudaFuncAttributeMaxDynamicSharedMemorySize, ATT_SMEM);

    // fused prep: mask pack + weight casts + input casts
    prep_kernel<<<NB_PREP, 256>>>(mask, gmb, Wq, Wk, Wv, Wo, gwb,
                                  Qin, Kin, Vin, gab);

    // merged Q/K/V projection GEMM (1152 CTAs)
    gemm_tc_kernel<true, false, true><<<dim3(DM/128, M_TOT/128, 3), 256, GEMM_SMEM>>>(
        gab, gwb, bq, bk, bv, nullptr, gqkv);

    // attention (writes ctx bf16 into g_ab slice 0)
    attn_tc_kernel<<<dim3(SS / 128, NH, BB), 256, ATT_SMEM>>>(gmb);

    // output projection + residual
    gemm_tc_kernel<false, true, false><<<dim3(DM/128, M_TOT/128), 256, GEMM_SMEM>>>(
        gab, gwb + 3*(size_t)DM*DM, bo, nullptr, nullptr, Qin, gtmp);

    ln_kernel<<<M_TOT, 256>>>(gtmp, gamma, beta, out);
}

// round 14
// speedup vs baseline: 1.0510x; 1.0510x over previous
#include <cuda_runtime.h>
#include <cuda_bf16.h>
#include <math.h>
#include <stdint.h>

#define BB     4
#define SS     2048
#define DM     768
#define NH     12
#define DKH    64
#define M_TOT  (BB*SS)   // 8192

// -------- scratch (static device arrays; no runtime allocation) --------
__device__ __nv_bfloat16 g_qkvb[3*M_TOT*DM];   // Q,K,V projections (bf16)
__device__ __nv_bfloat16 g_ab[3*M_TOT*DM];     // cast inputs / ctx (slice 0)
__device__ __nv_bfloat16 g_wb[4*DM*DM];        // cast weights x4
__device__ float    g_tmp[M_TOT*DM];
__device__ uint32_t g_mbits[BB*SS*(SS/32)];    // packed mask bits

// ============================================================================
// helpers
// ============================================================================
__device__ __forceinline__ uint32_t smem_u32(const void* p) {
    return (uint32_t)__cvta_generic_to_shared(p);
}
__device__ __forceinline__ void ldsm4(uint32_t& r0, uint32_t& r1, uint32_t& r2, uint32_t& r3, uint32_t addr) {
    asm volatile("ldmatrix.sync.aligned.m8n8.x4.shared.b16 {%0,%1,%2,%3}, [%4];"
                 : "=r"(r0), "=r"(r1), "=r"(r2), "=r"(r3) : "r"(addr));
}
__device__ __forceinline__ void ldsm4t(uint32_t& r0, uint32_t& r1, uint32_t& r2, uint32_t& r3, uint32_t addr) {
    asm volatile("ldmatrix.sync.aligned.m8n8.x4.trans.shared.b16 {%0,%1,%2,%3}, [%4];"
                 : "=r"(r0), "=r"(r1), "=r"(r2), "=r"(r3) : "r"(addr));
}
__device__ __forceinline__ void mma_bf16(float* c, uint32_t a0, uint32_t a1, uint32_t a2, uint32_t a3,
                                         uint32_t b0, uint32_t b1) {
    asm volatile("mma.sync.aligned.m16n8k16.row.col.f32.bf16.bf16.f32 "
                 "{%0,%1,%2,%3},{%4,%5,%6,%7},{%8,%9},{%0,%1,%2,%3};"
                 : "+f"(c[0]), "+f"(c[1]), "+f"(c[2]), "+f"(c[3])
                 : "r"(a0), "r"(a1), "r"(a2), "r"(a3), "r"(b0), "r"(b1));
}
__device__ __forceinline__ uint32_t pack_bf16(float x, float y) {
    __nv_bfloat162 p;
    p.x = __float2bfloat16(x);
    p.y = __float2bfloat16(y);
    return *(uint32_t*)&p;
}
__device__ __forceinline__ void cpasync16(uint32_t dst, const void* src) {
    asm volatile("cp.async.cg.shared.global [%0], [%1], 16;" :: "r"(dst), "l"(src));
}
__device__ __forceinline__ void cp_commit() { asm volatile("cp.async.commit_group;"); }
template<int N> __device__ __forceinline__ void cp_wait() {
    asm volatile("cp.async.wait_group %0;" :: "n"(N));
}

// ============================================================================
// Fused prep kernel: role by blockIdx.x range.
// ============================================================================
#define NB_MASK 4096
#define NB_WCST 2304   // 4 * 576
#define NB_ICST 18432  // 3 * 6144
#define NB_PREP (NB_MASK + NB_WCST + NB_ICST)

__global__ __launch_bounds__(256) void prep_kernel(
    const int* __restrict__ mask, uint32_t* __restrict__ bits,
    const float* __restrict__ w0, const float* __restrict__ w1,
    const float* __restrict__ w2, const float* __restrict__ w3,
    __nv_bfloat16* __restrict__ wdst,
    const float* __restrict__ x0, const float* __restrict__ x1,
    const float* __restrict__ x2, __nv_bfloat16* __restrict__ xdst)
{
    const int bid = blockIdx.x;
    const int tid = threadIdx.x;

    if (bid < NB_MASK) {
        const int warp = (bid * 256 + tid) >> 5;
        const int lane = tid & 31;
        const size_t base = (size_t)warp * 16 * 32;
        #pragma unroll
        for (int i = 0; i < 16; i++) {
            int v = mask[base + i * 32 + lane];
            unsigned bal = __ballot_sync(0xffffffffu, v != 0);
            if (lane == 0) bits[warp * 16 + i] = bal;
        }
    } else if (bid < NB_MASK + NB_WCST) {
        const int idx = bid - NB_MASK;
        const int z   = idx / 576;
        const int blk = idx % 576;
        const float* x = (z == 0) ? w0 : (z == 1) ? w1 : (z == 2) ? w2 : w3;
        const size_t i = ((size_t)blk * 256 + tid) * 4;
        float4 v = *(const float4*)(x + i);
        __nv_bfloat16 h[4];
        h[0] = __float2bfloat16(v.x);
        h[1] = __float2bfloat16(v.y);
        h[2] = __float2bfloat16(v.z);
        h[3] = __float2bfloat16(v.w);
        *(uint2*)(wdst + (size_t)z * DM * DM + i) = *(uint2*)h;
    } else {
        const int idx = bid - NB_MASK - NB_WCST;
        const int z   = idx / 6144;
        const int blk = idx % 6144;
        const float* x = (z == 0) ? x0 : (z == 1) ? x1 : x2;
        const size_t i = ((size_t)blk * 256 + tid) * 4;
        float4 v = *(const float4*)(x + i);
        __nv_bfloat16 h[4];
        h[0] = __float2bfloat16(v.x);
        h[1] = __float2bfloat16(v.y);
        h[2] = __float2bfloat16(v.z);
        h[3] = __float2bfloat16(v.w);
        *(uint2*)(xdst + (size_t)z * M_TOT * DM + i) = *(uint2*)h;
    }
}

// ============================================================================
// bf16 tensor-core GEMM — R11 mainloop restored exactly:
// 3-stage cp.async ring, ONE barrier per k-step, B ldsm interleaved per n-half.
// 128x128 tile, BK=32, 8 warps (2m x 4n), warp tile 64x32.
// ============================================================================
#define AST 40    // A smem row stride (bf16): 80B -> ldsm conflict-free
#define BST 136   // B smem row stride (bf16): 272B -> ldsm.trans conflict-free
#define BK  32
#define NKT 24    // 768/32
#define GSTAGES 3
#define A_STAGE_BYTES (128*AST*2)   // 10240
#define B_STAGE_BYTES (BK*BST*2)    // 8704
#define GEMM_SMEM (GSTAGES*(A_STAGE_BYTES+B_STAGE_BYTES))   // 56832

template<bool MULTI, bool RESID, bool OUTBF16>
__global__ __launch_bounds__(256, 2) void gemm_tc_kernel(
    const __nv_bfloat16* __restrict__ Ag, const __nv_bfloat16* __restrict__ Wg,
    const float* __restrict__ b0, const float* __restrict__ b1,
    const float* __restrict__ b2,
    const float* __restrict__ resid, void* __restrict__ Cout)
{
    extern __shared__ __nv_bfloat16 smg[];
    const uint32_t as0 = smem_u32(smg);
    const uint32_t bs0 = as0 + GSTAGES * A_STAGE_BYTES;

    const int z = MULTI ? blockIdx.z : 0;
    const float* bias = MULTI ? ((z == 0) ? b0 : (z == 1) ? b1 : b2) : b0;
    const size_t a_base = (size_t)z * M_TOT * DM;
    const size_t w_base = (size_t)z * DM * DM;

    const int tid  = threadIdx.x;
    const int wid  = tid >> 5;
    const int lane = tid & 31;
    const int m0   = blockIdx.y * 128;
    const int n0   = blockIdx.x * 128;
    const int warp_m = (wid & 1) * 64;
    const int warp_n = (wid >> 1) * 32;

    const int sar = tid >> 1;            // A row 0..127
    const int sac = (tid & 1) * 16;      // A col 0 or 16
    const int sbr = tid >> 3;            // B k row 0..31
    const int sbc = (tid & 7) * 16;      // B n col

    const uint32_t a_off = (uint32_t)(sar * AST + sac) * 2;
    const uint32_t b_off = (uint32_t)(sbr * BST + sbc) * 2;

    const __nv_bfloat16* a_src = Ag + a_base + (size_t)(m0 + sar) * DM + sac;
    const __nv_bfloat16* b_src = Wg + w_base + (size_t)sbr * DM + n0 + sbc;

    const int lrow = lane & 7;
    const int lsel = lane >> 3;
    const int arow_f = lrow + ((lsel & 1) ? 8 : 0);
    const int akb    = (lsel & 2) ? 16 : 0;
    const int bkr    = lrow + ((lsel & 1) ? 8 : 0);
    const int bn_sub = (lsel & 2) ? 8 : 0;

    float acc[4][4][4] = {};

    auto fill = [&](int kt) {
        const int s = kt % GSTAGES;
        const uint32_t sa = as0 + (uint32_t)(s * A_STAGE_BYTES);
        const uint32_t sb = bs0 + (uint32_t)(s * B_STAGE_BYTES);
        const int k0 = kt * BK;
        cpasync16(sa + a_off,      a_src + k0);
        cpasync16(sa + a_off + 16, a_src + k0 + 8);
        cpasync16(sb + b_off,      b_src + (size_t)k0 * DM);
        cpasync16(sb + b_off + 16, b_src + (size_t)k0 * DM + 8);
        cp_commit();
    };

    fill(0);
    fill(1);

    for (int kt = 0; kt < NKT; kt++) {
        if (kt == NKT - 1) cp_wait<0>(); else cp_wait<GSTAGES - 2>();
        __syncthreads();
        if (kt + GSTAGES - 1 < NKT) fill(kt + GSTAGES - 1);

        const int s = kt % GSTAGES;
        const uint32_t as_s = as0 + (uint32_t)(s * A_STAGE_BYTES);
        const uint32_t bs_s = bs0 + (uint32_t)(s * B_STAGE_BYTES);

        #pragma unroll
        for (int kk = 0; kk < 2; kk++) {
            uint32_t af[4][4];
            #pragma unroll
            for (int t = 0; t < 4; t++)
                ldsm4(af[t][0], af[t][1], af[t][2], af[t][3],
                      as_s + (uint32_t)((warp_m + t*16 + arow_f) * AST * 2 + kk*32 + akb));
            #pragma unroll
            for (int u = 0; u < 2; u++) {
                uint32_t r0, r1, r2, r3;
                ldsm4t(r0, r1, r2, r3,
                       bs_s + (uint32_t)((kk*16 + bkr) * BST * 2 + (warp_n + u*16 + bn_sub) * 2));
                #pragma unroll
                for (int t = 0; t < 4; t++) {
                    mma_bf16(acc[t][2*u],   af[t][0], af[t][1], af[t][2], af[t][3], r0, r1);
                    mma_bf16(acc[t][2*u+1], af[t][0], af[t][1], af[t][2], af[t][3], r2, r3);
                }
            }
        }
    }

    // epilogue
    const int g  = lane >> 2;
    const int t4 = lane & 3;
    #pragma unroll
    for (int t = 0; t < 4; t++) {
        #pragma unroll
        for (int n = 0; n < 4; n++) {
            int row0 = m0 + warp_m + t*16 + g;
            int row1 = row0 + 8;
            int col  = n0 + warp_n + n*8 + t4*2;
            float2 bi = *(const float2*)(bias + col);
            float2 o0, o1;
            o0.x = acc[t][n][0] + bi.x;  o0.y = acc[t][n][1] + bi.y;
            o1.x = acc[t][n][2] + bi.x;  o1.y = acc[t][n][3] + bi.y;
            if (RESID) {
                float2 r0 = *(const float2*)(resid + (size_t)row0 * DM + col);
                float2 r1 = *(const float2*)(resid + (size_t)row1 * DM + col);
                o0.x += r0.x; o0.y += r0.y;
                o1.x += r1.x; o1.y += r1.y;
            }
            if (OUTBF16) {
                __nv_bfloat16* C = (__nv_bfloat16*)Cout + (size_t)z * M_TOT * DM;
                *(uint32_t*)(C + (size_t)row0 * DM + col) = pack_bf16(o0.x, o0.y);
                *(uint32_t*)(C + (size_t)row1 * DM + col) = pack_bf16(o1.x, o1.y);
            } else {
                float* C = (float*)Cout;
                *(float2*)(C + (size_t)row0 * DM + col) = o0;
                *(float2*)(C + (size_t)row1 * DM + col) = o1;
            }
        }
    }
}

// ============================================================================
// Tensor-core flash attention, 3-stage cp.async ring, ONE barrier per tile.
// (unchanged from R11)
// ============================================================================
#define KST 72
#define ATT_STAGE_BYTES (2 * 64 * KST * 2)   // 18432
#define ASTAGES 3
#define ATT_SMEM (ASTAGES * ATT_STAGE_BYTES) // 55296
#define NTILES (SS/64)

__global__ __launch_bounds__(256, 2) void attn_tc_kernel(const uint32_t* __restrict__ mbits)
{
    extern __shared__ __nv_bfloat16 sma[];

    const int tid  = threadIdx.x;
    const int wid  = tid >> 5;
    const int lane = tid & 31;
    const int b    = blockIdx.z;
    const int h    = blockIdx.y;
    const int q0   = blockIdx.x * 128;
    const int g    = lane >> 2;
    const int t4   = lane & 3;

    const __nv_bfloat16* qg = g_qkvb + 0 * (size_t)M_TOT * DM;
    const __nv_bfloat16* kg = g_qkvb + 1 * (size_t)M_TOT * DM + (size_t)(b * SS) * DM + h * DKH;
    const __nv_bfloat16* vg = g_qkvb + 2 * (size_t)M_TOT * DM + (size_t)(b * SS) * DM + h * DKH;

    {
        const int r  = tid >> 1;
        const int hh = (tid & 1) * 32;
        const uint4* src = (const uint4*)(qg + (size_t)(b * SS + q0 + r) * DM + h * DKH + hh);
        uint4* dst = (uint4*)(sma + r * KST + hh);
        dst[0] = src[0]; dst[1] = src[1]; dst[2] = src[2]; dst[3] = src[3];
    }
    __syncthreads();

    uint32_t qa[4][4];
    {
        const uint32_t base = smem_u32(sma);
        const int row  = wid * 16 + (lane & 15);
        const int colh = (lane >> 4) * 8;
        #pragma unroll
        for (int j = 0; j < 4; j++)
            ldsm4(qa[j][0], qa[j][1], qa[j][2], qa[j][3],
                  base + (uint32_t)((row * KST + j * 16 + colh) * 2));
    }
    __syncthreads();

    float o[8][4] = {};
    float ls0 = 0.f, ls1 = 0.f;

    const uint32_t* mrow0 = mbits + ((size_t)(b * SS + q0 + wid * 16 + g)) * (SS/32);
    const uint32_t* mrow1 = mrow0 + 8 * (SS/32);

    const uint32_t sb = smem_u32(sma);

    const int krow = (lane & 7) + ((lane >> 4) ? 8 : 0);
    const int kcol = ((lane >> 3) & 1) * 8;
    const int vrow = (lane & 7) + (((lane >> 3) & 1) ? 8 : 0);
    const int vcol = (lane >> 4) * 8;
    const uint32_t k_lane_off = (uint32_t)((krow * KST + kcol) * 2);
    const uint32_t v_lane_off = (uint32_t)((vrow * KST + vcol) * 2) + (uint32_t)(64*KST*2);

    const int c0   = tid * 2;
    const int srow = c0 >> 3;
    const int scol = (c0 & 7) * 8;
    const uint32_t st_off = (uint32_t)((srow * KST + scol) * 2);

    auto fill = [&](int kt) {
        const uint32_t base = sb + (uint32_t)((kt % ASTAGES) * ATT_STAGE_BYTES);
        const __nv_bfloat16* kp = kg + (size_t)(kt * 64 + srow) * DM + scol;
        const __nv_bfloat16* vp = vg + (size_t)(kt * 64 + srow) * DM + scol;
        cpasync16(base + st_off, kp);
        cpasync16(base + st_off + 16, kp + 8);
        cpasync16(base + (uint32_t)(64*KST*2) + st_off, vp);
        cpasync16(base + (uint32_t)(64*KST*2) + st_off + 16, vp + 8);
        cp_commit();
    };

    fill(0);
    fill(1);

    for (int kt = 0; kt < NTILES; kt++) {
        if (kt == NTILES - 1) cp_wait<0>(); else cp_wait<ASTAGES - 2>();
        __syncthreads();
        if (kt + ASTAGES - 1 < NTILES) fill(kt + ASTAGES - 1);

        const uint32_t stage = sb + (uint32_t)((kt % ASTAGES) * ATT_STAGE_BYTES);
        const uint32_t kaddr0 = stage + k_lane_off;
        const uint32_t vaddr0 = stage + v_lane_off;

        float c[8][4] = {};
        #pragma unroll
        for (int np = 0; np < 4; np++) {
            #pragma unroll
            for (int j = 0; j < 4; j++) {
                uint32_t r0, r1, r2, r3;
                ldsm4(r0, r1, r2, r3, kaddr0 + (uint32_t)((np*16*KST + j*16) * 2));
                mma_bf16(c[2*np],   qa[j][0], qa[j][1], qa[j][2], qa[j][3], r0, r1);
                mma_bf16(c[2*np+1], qa[j][0], qa[j][1], qa[j][2], qa[j][3], r2, r3);
            }
        }

        const int k0 = kt * 64;
        const int kw = k0 >> 5;
        const uint32_t m0a = mrow0[kw], m0b = mrow0[kw+1];
        const uint32_t m1a = mrow1[kw], m1b = mrow1[kw+1];
        const float SC = 0.125f * 1.44269504088896340736f;
        #pragma unroll
        for (int nt = 0; nt < 8; nt++) {
            const int colb = nt * 8 + 2 * t4;
            const uint32_t w0 = (colb & 32) ? m0b : m0a;
            const uint32_t w1 = (colb & 32) ? m1b : m1a;
            const int bit = colb & 31;
            float p0 = ((w0 >> bit)     & 1u) ? 0.f : exp2f(c[nt][0] * SC);
            float p1 = ((w0 >> (bit+1)) & 1u) ? 0.f : exp2f(c[nt][1] * SC);
            float p2 = ((w1 >> bit)     & 1u) ? 0.f : exp2f(c[nt][2] * SC);
            float p3 = ((w1 >> (bit+1)) & 1u) ? 0.f : exp2f(c[nt][3] * SC);
            ls0 += p0 + p1;
            ls1 += p2 + p3;
            c[nt][0] = p0; c[nt][1] = p1; c[nt][2] = p2; c[nt][3] = p3;
        }

        uint32_t pa[4][4];
        #pragma unroll
        for (int j = 0; j < 4; j++) {
            pa[j][0] = pack_bf16(c[2*j][0],   c[2*j][1]);
            pa[j][1] = pack_bf16(c[2*j][2],   c[2*j][3]);
            pa[j][2] = pack_bf16(c[2*j+1][0], c[2*j+1][1]);
            pa[j][3] = pack_bf16(c[2*j+1][2], c[2*j+1][3]);
        }

        #pragma unroll
        for (int np = 0; np < 4; np++) {
            #pragma unroll
            for (int j = 0; j < 4; j++) {
                uint32_t r0, r1, r2, r3;
                ldsm4t(r0, r1, r2, r3, vaddr0 + (uint32_t)((j*16*KST + np*16) * 2));
                mma_bf16(o[2*np],   pa[j][0], pa[j][1], pa[j][2], pa[j][3], r0, r1);
                mma_bf16(o[2*np+1], pa[j][0], pa[j][1], pa[j][2], pa[j][3], r2, r3);
            }
        }
    }

    ls0 += __shfl_xor_sync(0xffffffffu, ls0, 1);
    ls0 += __shfl_xor_sync(0xffffffffu, ls0, 2);
    ls1 += __shfl_xor_sync(0xffffffffu, ls1, 1);
    ls1 += __shfl_xor_sync(0xffffffffu, ls1, 2);
    const float inv0 = 1.f / ls0;
    const float inv1 = 1.f / ls1;

    const size_t r0off = (size_t)(b * SS + q0 + wid * 16 + g) * DM + h * DKH;
    const size_t r1off = r0off + 8 * DM;
    #pragma unroll
    for (int nt = 0; nt < 8; nt++) {
        const int col = nt * 8 + 2 * t4;
        *(uint32_t*)(g_ab + r0off + col) = pack_bf16(o[nt][0] * inv0, o[nt][1] * inv0);
        *(uint32_t*)(g_ab + r1off + col) = pack_bf16(o[nt][2] * inv1, o[nt][3] * inv1);
    }
}

// ============================================================================
// LayerNorm: 1 block per row, 256 threads, 3 elements each
// ============================================================================
__global__ __launch_bounds__(256) void ln_kernel(
    const float* __restrict__ x,
    const float* __restrict__ gamma, const float* __restrict__ beta,
    float* __restrict__ out)
{
    const int row = blockIdx.x;
    const int tid = threadIdx.x;
    const float* xr = x + (size_t)row * DM;

    float v0 = xr[tid];
    float v1 = xr[tid + 256];
    float v2 = xr[tid + 512];
    float s  = v0 + v1 + v2;
    float sq = v0 * v0 + v1 * v1 + v2 * v2;

    #pragma unroll
    for (int o = 16; o > 0; o >>= 1) {
        s  += __shfl_xor_sync(0xffffffffu, s,  o);
        sq += __shfl_xor_sync(0xffffffffu, sq, o);
    }
    __shared__ float reds[8], redq[8];
    const int wid = tid >> 5, lid = tid & 31;
    if (lid == 0) { reds[wid] = s; redq[wid] = sq; }
    __syncthreads();
    float ts = 0.f, tq = 0.f;
    #pragma unroll
    for (int i = 0; i < 8; i++) { ts += reds[i]; tq += redq[i]; }

    const float mu  = ts * (1.f / DM);
    const float var = tq * (1.f / DM) - mu * mu;
    const float rs  = rsqrtf(var + 1e-5f);

    float* orow = out + (size_t)row * DM;
    orow[tid]       = (v0 - mu) * rs * gamma[tid]       + beta[tid];
    orow[tid + 256] = (v1 - mu) * rs * gamma[tid + 256] + beta[tid + 256];
    orow[tid + 512] = (v2 - mu) * rs * gamma[tid + 512] + beta[tid + 512];
}

// ============================================================================
// Launch
// ============================================================================
extern "C" void kernel_launch(void* const* d_in, const int* in_sizes, int n_in,
                              void* d_out, int out_size)
{
    const float* Qin  = (const float*)d_in[0];
    const float* Kin  = (const float*)d_in[1];
    const float* Vin  = (const float*)d_in[2];
    const int*   mask = (const int*)d_in[3];
    const float* Wq = (const float*)d_in[4];
    const float* bq = (const float*)d_in[5];
    const float* Wk = (const float*)d_in[6];
    const float* bk = (const float*)d_in[7];
    const float* Wv = (const float*)d_in[8];
    const float* bv = (const float*)d_in[9];
    const float* Wo = (const float*)d_in[10];
    const float* bo = (const float*)d_in[11];
    const float* gamma = (const float*)d_in[12];
    const float* beta  = (const float*)d_in[13];
    float* out = (float*)d_out;

    __nv_bfloat16 *gqkv, *gab, *gwb;
    float* gtmp;
    uint32_t* gmb;
    cudaGetSymbolAddress((void**)&gqkv, g_qkvb);
    cudaGetSymbolAddress((void**)&gab,  g_ab);
    cudaGetSymbolAddress((void**)&gwb,  g_wb);
    cudaGetSymbolAddress((void**)&gtmp, g_tmp);
    cudaGetSymbolAddress((void**)&gmb,  g_mbits);

    cudaFuncSetAttribute(gemm_tc_kernel<true, false, true>,
                         cudaFuncAttributeMaxDynamicSharedMemorySize, GEMM_SMEM);
    cudaFuncSetAttribute(gemm_tc_kernel<false, true, false>,
                         cudaFuncAttributeMaxDynamicSharedMemorySize, GEMM_SMEM);
    cudaFuncSetAttribute(attn_tc_kernel,
                         cudaFuncAttributeMaxDynamicSharedMemorySize, ATT_SMEM);

    // fused prep: mask pack + weight casts + input casts
    prep_kernel<<<NB_PREP, 256>>>(mask, gmb, Wq, Wk, Wv, Wo, gwb,
                                  Qin, Kin, Vin, gab);

    // merged Q/K/V projection GEMM (1152 CTAs)
    gemm_tc_kernel<true, false, true><<<dim3(DM/128, M_TOT/128, 3), 256, GEMM_SMEM>>>(
        gab, gwb, bq, bk, bv, nullptr, gqkv);

    // attention (writes ctx bf16 into g_ab slice 0)
    attn_tc_kernel<<<dim3(SS / 128, NH, BB), 256, ATT_SMEM>>>(gmb);

    // output projection + residual
    gemm_tc_kernel<false, true, false><<<dim3(DM/128, M_TOT/128), 256, GEMM_SMEM>>>(
        gab, gwb + 3*(size_t)DM*DM, bo, nullptr, nullptr, Qin, gtmp);

    ln_kernel<<<M_TOT, 256>>>(gtmp, gamma, beta, out);
}

// round 16
// speedup vs baseline: 1.0709x; 1.0189x over previous
#include <cuda_runtime.h>
#include <cuda_bf16.h>
#include <math.h>
#include <stdint.h>

#define BB     4
#define SS     2048
#define DM     768
#define NH     12
#define DKH    64
#define M_TOT  (BB*SS)   // 8192

// -------- scratch (static device arrays; no runtime allocation) --------
__device__ __nv_bfloat16 g_qkvb[3*M_TOT*DM];   // Q,K,V projections (bf16)
__device__ __nv_bfloat16 g_ab[3*M_TOT*DM];     // cast inputs / ctx (slice 0)
__device__ __nv_bfloat16 g_wb[4*DM*DM];        // cast weights x4
__device__ float    g_tmp[M_TOT*DM];
__device__ uint32_t g_mbits[BB*SS*(SS/32)];    // packed mask bits

// ============================================================================
// helpers
// ============================================================================
__device__ __forceinline__ uint32_t smem_u32(const void* p) {
    return (uint32_t)__cvta_generic_to_shared(p);
}
__device__ __forceinline__ void ldsm4(uint32_t& r0, uint32_t& r1, uint32_t& r2, uint32_t& r3, uint32_t addr) {
    asm volatile("ldmatrix.sync.aligned.m8n8.x4.shared.b16 {%0,%1,%2,%3}, [%4];"
                 : "=r"(r0), "=r"(r1), "=r"(r2), "=r"(r3) : "r"(addr));
}
__device__ __forceinline__ void ldsm4t(uint32_t& r0, uint32_t& r1, uint32_t& r2, uint32_t& r3, uint32_t addr) {
    asm volatile("ldmatrix.sync.aligned.m8n8.x4.trans.shared.b16 {%0,%1,%2,%3}, [%4];"
                 : "=r"(r0), "=r"(r1), "=r"(r2), "=r"(r3) : "r"(addr));
}
__device__ __forceinline__ void mma_bf16(float* c, uint32_t a0, uint32_t a1, uint32_t a2, uint32_t a3,
                                         uint32_t b0, uint32_t b1) {
    asm volatile("mma.sync.aligned.m16n8k16.row.col.f32.bf16.bf16.f32 "
                 "{%0,%1,%2,%3},{%4,%5,%6,%7},{%8,%9},{%0,%1,%2,%3};"
                 : "+f"(c[0]), "+f"(c[1]), "+f"(c[2]), "+f"(c[3])
                 : "r"(a0), "r"(a1), "r"(a2), "r"(a3), "r"(b0), "r"(b1));
}
__device__ __forceinline__ uint32_t pack_bf16(float x, float y) {
    __nv_bfloat162 p;
    p.x = __float2bfloat16(x);
    p.y = __float2bfloat16(y);
    return *(uint32_t*)&p;
}
__device__ __forceinline__ void cpasync16(uint32_t dst, const void* src) {
    asm volatile("cp.async.cg.shared.global [%0], [%1], 16;" :: "r"(dst), "l"(src));
}
__device__ __forceinline__ void cp_commit() { asm volatile("cp.async.commit_group;"); }
template<int N> __device__ __forceinline__ void cp_wait() {
    asm volatile("cp.async.wait_group %0;" :: "n"(N));
}

// ============================================================================
// Fused prep kernel: role by blockIdx.x range.
// ============================================================================
#define NB_MASK 4096
#define NB_WCST 2304   // 4 * 576
#define NB_ICST 18432  // 3 * 6144
#define NB_PREP (NB_MASK + NB_WCST + NB_ICST)

__global__ __launch_bounds__(256) void prep_kernel(
    const int* __restrict__ mask, uint32_t* __restrict__ bits,
    const float* __restrict__ w0, const float* __restrict__ w1,
    const float* __restrict__ w2, const float* __restrict__ w3,
    __nv_bfloat16* __restrict__ wdst,
    const float* __restrict__ x0, const float* __restrict__ x1,
    const float* __restrict__ x2, __nv_bfloat16* __restrict__ xdst)
{
    const int bid = blockIdx.x;
    const int tid = threadIdx.x;

    if (bid < NB_MASK) {
        const int warp = (bid * 256 + tid) >> 5;
        const int lane = tid & 31;
        const size_t base = (size_t)warp * 16 * 32;
        #pragma unroll
        for (int i = 0; i < 16; i++) {
            int v = mask[base + i * 32 + lane];
            unsigned bal = __ballot_sync(0xffffffffu, v != 0);
            if (lane == 0) bits[warp * 16 + i] = bal;
        }
    } else if (bid < NB_MASK + NB_WCST) {
        const int idx = bid - NB_MASK;
        const int z   = idx / 576;
        const int blk = idx % 576;
        const float* x = (z == 0) ? w0 : (z == 1) ? w1 : (z == 2) ? w2 : w3;
        const size_t i = ((size_t)blk * 256 + tid) * 4;
        float4 v = *(const float4*)(x + i);
        __nv_bfloat16 h[4];
        h[0] = __float2bfloat16(v.x);
        h[1] = __float2bfloat16(v.y);
        h[2] = __float2bfloat16(v.z);
        h[3] = __float2bfloat16(v.w);
        *(uint2*)(wdst + (size_t)z * DM * DM + i) = *(uint2*)h;
    } else {
        const int idx = bid - NB_MASK - NB_WCST;
        const int z   = idx / 6144;
        const int blk = idx % 6144;
        const float* x = (z == 0) ? x0 : (z == 1) ? x1 : x2;
        const size_t i = ((size_t)blk * 256 + tid) * 4;
        float4 v = *(const float4*)(x + i);
        __nv_bfloat16 h[4];
        h[0] = __float2bfloat16(v.x);
        h[1] = __float2bfloat16(v.y);
        h[2] = __float2bfloat16(v.z);
        h[3] = __float2bfloat16(v.w);
        *(uint2*)(xdst + (size_t)z * M_TOT * DM + i) = *(uint2*)h;
    }
}

// ============================================================================
// bf16 tensor-core GEMM — R11/R14 mainloop (measured-good), unchanged.
// ============================================================================
#define AST 40
#define BST 136
#define BK  32
#define NKT 24
#define GSTAGES 3
#define A_STAGE_BYTES (128*AST*2)
#define B_STAGE_BYTES (BK*BST*2)
#define GEMM_SMEM (GSTAGES*(A_STAGE_BYTES+B_STAGE_BYTES))

template<bool MULTI, bool RESID, bool OUTBF16>
__global__ __launch_bounds__(256, 2) void gemm_tc_kernel(
    const __nv_bfloat16* __restrict__ Ag, const __nv_bfloat16* __restrict__ Wg,
    const float* __restrict__ b0, const float* __restrict__ b1,
    const float* __restrict__ b2,
    const float* __restrict__ resid, void* __restrict__ Cout)
{
    extern __shared__ __nv_bfloat16 smg[];
    const uint32_t as0 = smem_u32(smg);
    const uint32_t bs0 = as0 + GSTAGES * A_STAGE_BYTES;

    const int z = MULTI ? blockIdx.z : 0;
    const float* bias = MULTI ? ((z == 0) ? b0 : (z == 1) ? b1 : b2) : b0;
    const size_t a_base = (size_t)z * M_TOT * DM;
    const size_t w_base = (size_t)z * DM * DM;

    const int tid  = threadIdx.x;
    const int wid  = tid >> 5;
    const int lane = tid & 31;
    const int m0   = blockIdx.y * 128;
    const int n0   = blockIdx.x * 128;
    const int warp_m = (wid & 1) * 64;
    const int warp_n = (wid >> 1) * 32;

    const int sar = tid >> 1;
    const int sac = (tid & 1) * 16;
    const int sbr = tid >> 3;
    const int sbc = (tid & 7) * 16;

    const uint32_t a_off = (uint32_t)(sar * AST + sac) * 2;
    const uint32_t b_off = (uint32_t)(sbr * BST + sbc) * 2;

    const __nv_bfloat16* a_src = Ag + a_base + (size_t)(m0 + sar) * DM + sac;
    const __nv_bfloat16* b_src = Wg + w_base + (size_t)sbr * DM + n0 + sbc;

    const int lrow = lane & 7;
    const int lsel = lane >> 3;
    const int arow_f = lrow + ((lsel & 1) ? 8 : 0);
    const int akb    = (lsel & 2) ? 16 : 0;
    const int bkr    = lrow + ((lsel & 1) ? 8 : 0);
    const int bn_sub = (lsel & 2) ? 8 : 0;

    float acc[4][4][4] = {};

    auto fill = [&](int kt) {
        const int s = kt % GSTAGES;
        const uint32_t sa = as0 + (uint32_t)(s * A_STAGE_BYTES);
        const uint32_t sb = bs0 + (uint32_t)(s * B_STAGE_BYTES);
        const int k0 = kt * BK;
        cpasync16(sa + a_off,      a_src + k0);
        cpasync16(sa + a_off + 16, a_src + k0 + 8);
        cpasync16(sb + b_off,      b_src + (size_t)k0 * DM);
        cpasync16(sb + b_off + 16, b_src + (size_t)k0 * DM + 8);
        cp_commit();
    };

    fill(0);
    fill(1);

    for (int kt = 0; kt < NKT; kt++) {
        if (kt == NKT - 1) cp_wait<0>(); else cp_wait<GSTAGES - 2>();
        __syncthreads();
        if (kt + GSTAGES - 1 < NKT) fill(kt + GSTAGES - 1);

        const int s = kt % GSTAGES;
        const uint32_t as_s = as0 + (uint32_t)(s * A_STAGE_BYTES);
        const uint32_t bs_s = bs0 + (uint32_t)(s * B_STAGE_BYTES);

        #pragma unroll
        for (int kk = 0; kk < 2; kk++) {
            uint32_t af[4][4];
            #pragma unroll
            for (int t = 0; t < 4; t++)
                ldsm4(af[t][0], af[t][1], af[t][2], af[t][3],
                      as_s + (uint32_t)((warp_m + t*16 + arow_f) * AST * 2 + kk*32 + akb));
            #pragma unroll
            for (int u = 0; u < 2; u++) {
                uint32_t r0, r1, r2, r3;
                ldsm4t(r0, r1, r2, r3,
                       bs_s + (uint32_t)((kk*16 + bkr) * BST * 2 + (warp_n + u*16 + bn_sub) * 2));
                #pragma unroll
                for (int t = 0; t < 4; t++) {
                    mma_bf16(acc[t][2*u],   af[t][0], af[t][1], af[t][2], af[t][3], r0, r1);
                    mma_bf16(acc[t][2*u+1], af[t][0], af[t][1], af[t][2], af[t][3], r2, r3);
                }
            }
        }
    }

    const int g  = lane >> 2;
    const int t4 = lane & 3;
    #pragma unroll
    for (int t = 0; t < 4; t++) {
        #pragma unroll
        for (int n = 0; n < 4; n++) {
            int row0 = m0 + warp_m + t*16 + g;
            int row1 = row0 + 8;
            int col  = n0 + warp_n + n*8 + t4*2;
            float2 bi = *(const float2*)(bias + col);
            float2 o0, o1;
            o0.x = acc[t][n][0] + bi.x;  o0.y = acc[t][n][1] + bi.y;
            o1.x = acc[t][n][2] + bi.x;  o1.y = acc[t][n][3] + bi.y;
            if (RESID) {
                float2 r0 = *(const float2*)(resid + (size_t)row0 * DM + col);
                float2 r1 = *(const float2*)(resid + (size_t)row1 * DM + col);
                o0.x += r0.x; o0.y += r0.y;
                o1.x += r1.x; o1.y += r1.y;
            }
            if (OUTBF16) {
                __nv_bfloat16* C = (__nv_bfloat16*)Cout + (size_t)z * M_TOT * DM;
                *(uint32_t*)(C + (size_t)row0 * DM + col) = pack_bf16(o0.x, o0.y);
                *(uint32_t*)(C + (size_t)row1 * DM + col) = pack_bf16(o1.x, o1.y);
            } else {
                float* C = (float*)Cout;
                *(float2*)(C + (size_t)row0 * DM + col) = o0;
                *(float2*)(C + (size_t)row1 * DM + col) = o1;
            }
        }
    }
}

// ============================================================================
// Tensor-core flash attention — chunk-fused mainloop:
// per 16-key chunk: QK MMA -> softmax -> PV MMA (fine-grain pipe mixing).
// 3-stage cp.async ring, ONE barrier per tile (unchanged skeleton).
// ============================================================================
#define KST 72
#define ATT_STAGE_BYTES (2 * 64 * KST * 2)   // 18432
#define ASTAGES 3
#define ATT_SMEM (ASTAGES * ATT_STAGE_BYTES) // 55296
#define NTILES (SS/64)

__global__ __launch_bounds__(256, 2) void attn_tc_kernel(const uint32_t* __restrict__ mbits)
{
    extern __shared__ __nv_bfloat16 sma[];

    const int tid  = threadIdx.x;
    const int wid  = tid >> 5;
    const int lane = tid & 31;
    const int b    = blockIdx.z;
    const int h    = blockIdx.y;
    const int q0   = blockIdx.x * 128;
    const int g    = lane >> 2;
    const int t4   = lane & 3;

    const __nv_bfloat16* qg = g_qkvb + 0 * (size_t)M_TOT * DM;
    const __nv_bfloat16* kg = g_qkvb + 1 * (size_t)M_TOT * DM + (size_t)(b * SS) * DM + h * DKH;
    const __nv_bfloat16* vg = g_qkvb + 2 * (size_t)M_TOT * DM + (size_t)(b * SS) * DM + h * DKH;

    {
        const int r  = tid >> 1;
        const int hh = (tid & 1) * 32;
        const uint4* src = (const uint4*)(qg + (size_t)(b * SS + q0 + r) * DM + h * DKH + hh);
        uint4* dst = (uint4*)(sma + r * KST + hh);
        dst[0] = src[0]; dst[1] = src[1]; dst[2] = src[2]; dst[3] = src[3];
    }
    __syncthreads();

    uint32_t qa[4][4];
    {
        const uint32_t base = smem_u32(sma);
        const int row  = wid * 16 + (lane & 15);
        const int colh = (lane >> 4) * 8;
        #pragma unroll
        for (int j = 0; j < 4; j++)
            ldsm4(qa[j][0], qa[j][1], qa[j][2], qa[j][3],
                  base + (uint32_t)((row * KST + j * 16 + colh) * 2));
    }
    __syncthreads();

    float o[8][4] = {};
    float ls0 = 0.f, ls1 = 0.f;

    const uint32_t* mrow0 = mbits + ((size_t)(b * SS + q0 + wid * 16 + g)) * (SS/32);
    const uint32_t* mrow1 = mrow0 + 8 * (SS/32);

    const uint32_t sb = smem_u32(sma);

    const int krow = (lane & 7) + ((lane >> 4) ? 8 : 0);
    const int kcol = ((lane >> 3) & 1) * 8;
    const int vrow = (lane & 7) + (((lane >> 3) & 1) ? 8 : 0);
    const int vcol = (lane >> 4) * 8;
    const uint32_t k_lane_off = (uint32_t)((krow * KST + kcol) * 2);
    const uint32_t v_lane_off = (uint32_t)((vrow * KST + vcol) * 2) + (uint32_t)(64*KST*2);

    const int c0i  = tid * 2;
    const int srow = c0i >> 3;
    const int scol = (c0i & 7) * 8;
    const uint32_t st_off = (uint32_t)((srow * KST + scol) * 2);

    auto fill = [&](int kt) {
        const uint32_t base = sb + (uint32_t)((kt % ASTAGES) * ATT_STAGE_BYTES);
        const __nv_bfloat16* kp = kg + (size_t)(kt * 64 + srow) * DM + scol;
        const __nv_bfloat16* vp = vg + (size_t)(kt * 64 + srow) * DM + scol;
        cpasync16(base + st_off, kp);
        cpasync16(base + st_off + 16, kp + 8);
        cpasync16(base + (uint32_t)(64*KST*2) + st_off, vp);
        cpasync16(base + (uint32_t)(64*KST*2) + st_off + 16, vp + 8);
        cp_commit();
    };

    fill(0);
    fill(1);

    const float SC = 0.125f * 1.44269504088896340736f;

    for (int kt = 0; kt < NTILES; kt++) {
        if (kt == NTILES - 1) cp_wait<0>(); else cp_wait<ASTAGES - 2>();
        __syncthreads();
        if (kt + ASTAGES - 1 < NTILES) fill(kt + ASTAGES - 1);

        const uint32_t stage = sb + (uint32_t)((kt % ASTAGES) * ATT_STAGE_BYTES);
        const uint32_t kaddr0 = stage + k_lane_off;
        const uint32_t vaddr0 = stage + v_lane_off;

        const int kw = (kt * 64) >> 5;
        const uint32_t m0a = mrow0[kw], m0b = mrow0[kw+1];
        const uint32_t m1a = mrow1[kw], m1b = mrow1[kw+1];

        // ---- fused per-16-key-chunk: QK mma -> softmax -> PV mma ----
        #pragma unroll
        for (int np = 0; np < 4; np++) {
            // QK for keys [np*16, np*16+16)
            float c0[4] = {}, c1[4] = {};
            #pragma unroll
            for (int j = 0; j < 4; j++) {
                uint32_t r0, r1, r2, r3;
                ldsm4(r0, r1, r2, r3, kaddr0 + (uint32_t)((np*16*KST + j*16) * 2));
                mma_bf16(c0, qa[j][0], qa[j][1], qa[j][2], qa[j][3], r0, r1);
                mma_bf16(c1, qa[j][0], qa[j][1], qa[j][2], qa[j][3], r2, r3);
            }

            // softmax for this chunk (nt = 2np, 2np+1)
            uint32_t pa[4];
            #pragma unroll
            for (int hh = 0; hh < 2; hh++) {
                float* ch = hh ? c1 : c0;
                const int colb = (2*np + hh) * 8 + 2 * t4;
                const uint32_t w0 = (colb & 32) ? m0b : m0a;
                const uint32_t w1 = (colb & 32) ? m1b : m1a;
                const int bit = colb & 31;
                float p0 = ((w0 >> bit)     & 1u) ? 0.f : exp2f(ch[0] * SC);
                float p1 = ((w0 >> (bit+1)) & 1u) ? 0.f : exp2f(ch[1] * SC);
                float p2 = ((w1 >> bit)     & 1u) ? 0.f : exp2f(ch[2] * SC);
                float p3 = ((w1 >> (bit+1)) & 1u) ? 0.f : exp2f(ch[3] * SC);
                ls0 += p0 + p1;
                ls1 += p2 + p3;
                pa[2*hh]   = pack_bf16(p0, p1);
                pa[2*hh+1] = pack_bf16(p2, p3);
            }

            // PV for this chunk across all d-column groups
            #pragma unroll
            for (int nd = 0; nd < 4; nd++) {
                uint32_t r0, r1, r2, r3;
                ldsm4t(r0, r1, r2, r3, vaddr0 + (uint32_t)((np*16*KST + nd*16) * 2));
                mma_bf16(o[2*nd],   pa[0], pa[1], pa[2], pa[3], r0, r1);
                mma_bf16(o[2*nd+1], pa[0], pa[1], pa[2], pa[3], r2, r3);
            }
        }
    }

    ls0 += __shfl_xor_sync(0xffffffffu, ls0, 1);
    ls0 += __shfl_xor_sync(0xffffffffu, ls0, 2);
    ls1 += __shfl_xor_sync(0xffffffffu, ls1, 1);
    ls1 += __shfl_xor_sync(0xffffffffu, ls1, 2);
    const float inv0 = 1.f / ls0;
    const float inv1 = 1.f / ls1;

    const size_t r0off = (size_t)(b * SS + q0 + wid * 16 + g) * DM + h * DKH;
    const size_t r1off = r0off + 8 * DM;
    #pragma unroll
    for (int nt = 0; nt < 8; nt++) {
        const int col = nt * 8 + 2 * t4;
        *(uint32_t*)(g_ab + r0off + col) = pack_bf16(o[nt][0] * inv0, o[nt][1] * inv0);
        *(uint32_t*)(g_ab + r1off + col) = pack_bf16(o[nt][2] * inv1, o[nt][3] * inv1);
    }
}

// ============================================================================
// LayerNorm: 1 block per row, 256 threads, 3 elements each
// ============================================================================
__global__ __launch_bounds__(256) void ln_kernel(
    const float* __restrict__ x,
    const float* __restrict__ gamma, const float* __restrict__ beta,
    float* __restrict__ out)
{
    const int row = blockIdx.x;
    const int tid = threadIdx.x;
    const float* xr = x + (size_t)row * DM;

    float v0 = xr[tid];
    float v1 = xr[tid + 256];
    float v2 = xr[tid + 512];
    float s  = v0 + v1 + v2;
    float sq = v0 * v0 + v1 * v1 + v2 * v2;

    #pragma unroll
    for (int o = 16; o > 0; o >>= 1) {
        s  += __shfl_xor_sync(0xffffffffu, s,  o);
        sq += __shfl_xor_sync(0xffffffffu, sq, o);
    }
    __shared__ float reds[8], redq[8];
    const int wid = tid >> 5, lid = tid & 31;
    if (lid == 0) { reds[wid] = s; redq[wid] = sq; }
    __syncthreads();
    float ts = 0.f, tq = 0.f;
    #pragma unroll
    for (int i = 0; i < 8; i++) { ts += reds[i]; tq += redq[i]; }

    const float mu  = ts * (1.f / DM);
    const float var = tq * (1.f / DM) - mu * mu;
    const float rs  = rsqrtf(var + 1e-5f);

    float* orow = out + (size_t)row * DM;
    orow[tid]       = (v0 - mu) * rs * gamma[tid]       + beta[tid];
    orow[tid + 256] = (v1 - mu) * rs * gamma[tid + 256] + beta[tid + 256];
    orow[tid + 512] = (v2 - mu) * rs * gamma[tid + 512] + beta[tid + 512];
}

// ============================================================================
// Launch
// ============================================================================
extern "C" void kernel_launch(void* const* d_in, const int* in_sizes, int n_in,
                              void* d_out, int out_size)
{
    const float* Qin  = (const float*)d_in[0];
    const float* Kin  = (const float*)d_in[1];
    const float* Vin  = (const float*)d_in[2];
    const int*   mask = (const int*)d_in[3];
    const float* Wq = (const float*)d_in[4];
    const float* bq = (const float*)d_in[5];
    const float* Wk = (const float*)d_in[6];
    const float* bk = (const float*)d_in[7];
    const float* Wv = (const float*)d_in[8];
    const float* bv = (const float*)d_in[9];
    const float* Wo = (const float*)d_in[10];
    const float* bo = (const float*)d_in[11];
    const float* gamma = (const float*)d_in[12];
    const float* beta  = (const float*)d_in[13];
    float* out = (float*)d_out;

    __nv_bfloat16 *gqkv, *gab, *gwb;
    float* gtmp;
    uint32_t* gmb;
    cudaGetSymbolAddress((void**)&gqkv, g_qkvb);
    cudaGetSymbolAddress((void**)&gab,  g_ab);
    cudaGetSymbolAddress((void**)&gwb,  g_wb);
    cudaGetSymbolAddress((void**)&gtmp, g_tmp);
    cudaGetSymbolAddress((void**)&gmb,  g_mbits);

    cudaFuncSetAttribute(gemm_tc_kernel<true, false, true>,
                         cudaFuncAttributeMaxDynamicSharedMemorySize, GEMM_SMEM);
    cudaFuncSetAttribute(gemm_tc_kernel<false, true, false>,
                         cudaFuncAttributeMaxDynamicSharedMemorySize, GEMM_SMEM);
    cudaFuncSetAttribute(attn_tc_kernel,
                         cudaFuncAttributeMaxDynamicSharedMemorySize, ATT_SMEM);

    // fused prep: mask pack + weight casts + input casts
    prep_kernel<<<NB_PREP, 256>>>(mask, gmb, Wq, Wk, Wv, Wo, gwb,
                                  Qin, Kin, Vin, gab);

    // merged Q/K/V projection GEMM (1152 CTAs)
    gemm_tc_kernel<true, false, true><<<dim3(DM/128, M_TOT/128, 3), 256, GEMM_SMEM>>>(
        gab, gwb, bq, bk, bv, nullptr, gqkv);

    // attention (writes ctx bf16 into g_ab slice 0)
    attn_tc_kernel<<<dim3(SS / 128, NH, BB), 256, ATT_SMEM>>>(gmb);

    // output projection + residual
    gemm_tc_kernel<false, true, false><<<dim3(DM/128, M_TOT/128), 256, GEMM_SMEM>>>(
        gab, gwb + 3*(size_t)DM*DM, bo, nullptr, nullptr, Qin, gtmp);

    ln_kernel<<<M_TOT, 256>>>(gtmp, gamma, beta, out);
}